// round 12
// baseline (speedup 1.0000x reference)
#include <cuda_runtime.h>
#include <cuda_bf16.h>

#define THREADS  256
#define ITEMS    4     // nnz per thread; finer tasks -> smaller last-wave tail
#define FULLMASK 0xffffffffu

__global__ void init_out_kernel(float* __restrict__ y,
                                const float* __restrict__ bias, int n) {
    int i  = blockIdx.x * blockDim.x + threadIdx.x;
    int i4 = i * 4;
    if (i4 + 4 <= n) {
        float4 b = *reinterpret_cast<const float4*>(bias + i4);
        *reinterpret_cast<float4*>(y + i4) = b;
    } else if (i4 < n) {
        for (int k = i4; k < n; k++) y[k] = bias[k];
    }
}

__global__ __launch_bounds__(THREADS)
void spmv_coo_kernel(const float* __restrict__ vals,
                     const float* __restrict__ x,
                     const int*   __restrict__ rows,
                     const int*   __restrict__ cols,
                     float*       __restrict__ y,
                     unsigned nnz,
                     unsigned nFullWarps) {   // warps whose whole 128-nnz span is in range
    const unsigned tid    = blockIdx.x * THREADS + threadIdx.x;
    const int      lane   = threadIdx.x & 31;
    const unsigned warpId = tid >> 5;

    if (warpId < nFullWarps) {
        const unsigned base = tid * ITEMS;

        // ---- Streaming loads (evict-first so x keeps L1 residency) ----
        int4   cc = __ldcs(reinterpret_cast<const int4*>(cols + base));
        int4   rr = __ldcs(reinterpret_cast<const int4*>(rows + base));
        float4 vv = __ldcs(reinterpret_cast<const float4*>(vals + base));

        // ---- Gather x: 4 independent random 4B loads ----
        float x0 = __ldg(&x[cc.x]);
        float x1 = __ldg(&x[cc.y]);
        float x2 = __ldg(&x[cc.z]);
        float x3 = __ldg(&x[cc.w]);

        int   r[ITEMS]  = {rr.x, rr.y, rr.z, rr.w};
        float v[ITEMS]  = {vv.x, vv.y, vv.z, vv.w};
        float xv[ITEMS] = {x0, x1, x2, x3};

        // ---- Per-thread segment scan; boundary in only ~6% of chunks ----
        float acc = 0.0f;
        int   cur = r[0];
        #pragma unroll
        for (int i = 0; i < ITEMS; i++) {
            if (r[i] != cur) {
                atomicAdd(&y[cur], acc);
                acc = 0.0f;
                cur = r[i];
            }
            acc = fmaf(v[i], xv[i], acc);
        }

        // ---- Warp segmented inclusive scan over tail accumulators.
        //      Rows sorted => equal tail rows are lane-contiguous. ----
        int lrprev = __shfl_up_sync(FULLMASK, cur, 1);
        unsigned headf = (lane == 0) || (cur != lrprev);

        float    vsum = acc;
        unsigned stop = headf;
        #pragma unroll
        for (int d = 1; d < 32; d <<= 1) {
            float    pv = __shfl_up_sync(FULLMASK, vsum, d);
            unsigned ps = __shfl_up_sync(FULLMASK, stop, d);
            if (lane >= d && !stop) { vsum += pv; stop = ps; }
        }
        unsigned hnext = __shfl_down_sync(FULLMASK, headf, 1);
        if (lane == 31 || hnext) atomicAdd(&y[cur], vsum);
    } else {
        // ---- Tail warp: scalar, bounds-checked, no collectives ----
        const unsigned base = tid * ITEMS;
        if (base >= nnz) return;
        unsigned cnt = nnz - base;
        if (cnt > ITEMS) cnt = ITEMS;

        float acc = 0.0f;
        int   cur = rows[base];
        for (unsigned k = 0; k < cnt; k++) {
            int   ri = rows[base + k];
            int   ci = cols[base + k];
            float vi = vals[base + k];
            if (ri != cur) {
                atomicAdd(&y[cur], acc);
                acc = 0.0f;
                cur = ri;
            }
            acc = fmaf(vi, __ldg(&x[ci]), acc);
        }
        atomicAdd(&y[cur], acc);
    }
}

extern "C" void kernel_launch(void* const* d_in, const int* in_sizes, int n_in,
                              void* d_out, int out_size) {
    // metadata order: vals[NNZ] f32, x[N_COLS] f32, bias[N_ROWS] f32,
    //                 rows[NNZ] i32, cols[NNZ] i32, n_rows (ignored)
    const float* vals = (const float*)d_in[0];
    const float* x    = (const float*)d_in[1];
    const float* bias = (const float*)d_in[2];
    const int*   rows = (const int*)d_in[3];
    const int*   cols = (const int*)d_in[4];
    float* y = (float*)d_out;

    unsigned nnz = (unsigned)in_sizes[0];
    int n_rows   = in_sizes[2];

    // 1) y = bias  (vectorized; d_out is poisoned before timing)
    {
        int quads = (n_rows + 3) / 4;
        int grid  = (quads + THREADS - 1) / THREADS;
        init_out_kernel<<<grid, THREADS>>>(y, bias, n_rows);
    }

    // 2) y += segment_sum(vals * x[cols]) — flat launch, one 4-nnz chunk/thread
    {
        const unsigned spanPerWarp = 32u * ITEMS;            // 128 nnz
        unsigned nFullWarps = nnz / spanPerWarp;             // fully in-range warps
        unsigned chunks = (nnz + ITEMS - 1) / ITEMS;
        unsigned grid   = (chunks + THREADS - 1) / THREADS;
        spmv_coo_kernel<<<grid, THREADS>>>(vals, x, rows, cols, y, nnz, nFullWarps);
    }
}